// round 1
// baseline (speedup 1.0000x reference)
#include <cuda_runtime.h>

// QCNN closed form:
// The reference circuit per layer k:
//   - fresh |0...0> state (10 wires)
//   - RX(x_w) on each wire, then RX(theta_w) on each wire
//       => per-wire RX(x_w + theta_w) acting on |0>, state stays a PRODUCT state
//   - CNOT chain (0,1)(1,2)...(8,9): basis permutation with new bit_w = XOR of bits 0..w
//   - <Z_w> after chain == <Z_0 Z_1 ... Z_w> before chain
//       => for a product state: prod_{j<=w} cos(x_j + theta_j)
// So each layer is just a prefix product of cosines, and the whole net is
//   6 x (prefix-prod of cos) -> sigmoid(x @ W + b).

#define NW 10
#define NLAYERS 6

__global__ __launch_bounds__(256) void qcnn_kernel(
    const float* __restrict__ inputs,   // (B, 10)
    const float* __restrict__ thetas,   // (6, 10)
    const float* __restrict__ W,        // (10, 4)
    const float* __restrict__ bias,     // (4,)
    float* __restrict__ out,            // (B, 4)
    int B)
{
    int b = blockIdx.x * blockDim.x + threadIdx.x;
    if (b >= B) return;

    // Load this batch element's 10 features.
    float x[NW];
    const float* row = inputs + (size_t)b * NW;
    #pragma unroll
    for (int w = 0; w < NW; w++) x[w] = __ldg(row + w);

    // 6 layers of prefix-product-of-cosines.
    #pragma unroll
    for (int k = 0; k < NLAYERS; k++) {
        float p = 1.0f;
        #pragma unroll
        for (int w = 0; w < NW; w++) {
            p *= cosf(x[w] + __ldg(thetas + k * NW + w));
            x[w] = p;
        }
    }

    // Final linear layer + sigmoid. W is (10, 4) row-major.
    float acc[4];
    #pragma unroll
    for (int o = 0; o < 4; o++) acc[o] = __ldg(bias + o);
    #pragma unroll
    for (int w = 0; w < NW; w++) {
        float xv = x[w];
        #pragma unroll
        for (int o = 0; o < 4; o++) acc[o] = fmaf(xv, __ldg(W + w * 4 + o), acc[o]);
    }

    float4 r;
    r.x = 1.0f / (1.0f + expf(-acc[0]));
    r.y = 1.0f / (1.0f + expf(-acc[1]));
    r.z = 1.0f / (1.0f + expf(-acc[2]));
    r.w = 1.0f / (1.0f + expf(-acc[3]));
    reinterpret_cast<float4*>(out)[b] = r;
}

extern "C" void kernel_launch(void* const* d_in, const int* in_sizes, int n_in,
                              void* d_out, int out_size) {
    const float* inputs = (const float*)d_in[0];  // (B, 10)
    const float* thetas = (const float*)d_in[1];  // (6, 10)
    const float* W      = (const float*)d_in[2];  // (10, 4)
    const float* bias   = (const float*)d_in[3];  // (4,)
    float* out = (float*)d_out;

    int B = in_sizes[0] / NW;  // 32768
    int threads = 256;
    int blocks = (B + threads - 1) / threads;
    qcnn_kernel<<<blocks, threads>>>(inputs, thetas, W, bias, out, B);
}

// round 2
// speedup vs baseline: 2.1643x; 2.1643x over previous
#include <cuda_runtime.h>

// QCNN closed form (see R0 derivation): each layer is a prefix product of
// cos(x_w + theta_w); then sigmoid(x @ W + b).
//
// R1 change: precise cosf was the bottleneck (latency-bound, 60 calls/thread,
// occ 12.5%). Switch to __cosf / __expf hardware intrinsics (RRO+MUFU, 2 SASS
// instrs each) and use 128-thread blocks so all 148 SMs get work.

#define NW 10
#define NLAYERS 6

__global__ __launch_bounds__(128) void qcnn_kernel(
    const float* __restrict__ inputs,   // (B, 10)
    const float* __restrict__ thetas,   // (6, 10)
    const float* __restrict__ W,        // (10, 4)
    const float* __restrict__ bias,     // (4,)
    float* __restrict__ out,            // (B, 4)
    int B)
{
    int b = blockIdx.x * blockDim.x + threadIdx.x;
    if (b >= B) return;

    // Load this batch element's 10 features.
    float x[NW];
    const float* row = inputs + (size_t)b * NW;
    #pragma unroll
    for (int w = 0; w < NW; w++) x[w] = __ldg(row + w);

    // 6 layers of prefix-product-of-cosines (fast MUFU cos).
    #pragma unroll
    for (int k = 0; k < NLAYERS; k++) {
        float p = 1.0f;
        #pragma unroll
        for (int w = 0; w < NW; w++) {
            p *= __cosf(x[w] + __ldg(thetas + k * NW + w));
            x[w] = p;
        }
    }

    // Final linear layer + sigmoid. W is (10, 4) row-major.
    float acc[4];
    #pragma unroll
    for (int o = 0; o < 4; o++) acc[o] = __ldg(bias + o);
    #pragma unroll
    for (int w = 0; w < NW; w++) {
        float xv = x[w];
        #pragma unroll
        for (int o = 0; o < 4; o++) acc[o] = fmaf(xv, __ldg(W + w * 4 + o), acc[o]);
    }

    float4 r;
    r.x = __frcp_rn(1.0f + __expf(-acc[0]));
    r.y = __frcp_rn(1.0f + __expf(-acc[1]));
    r.z = __frcp_rn(1.0f + __expf(-acc[2]));
    r.w = __frcp_rn(1.0f + __expf(-acc[3]));
    reinterpret_cast<float4*>(out)[b] = r;
}

extern "C" void kernel_launch(void* const* d_in, const int* in_sizes, int n_in,
                              void* d_out, int out_size) {
    const float* inputs = (const float*)d_in[0];  // (B, 10)
    const float* thetas = (const float*)d_in[1];  // (6, 10)
    const float* W      = (const float*)d_in[2];  // (10, 4)
    const float* bias   = (const float*)d_in[3];  // (4,)
    float* out = (float*)d_out;

    int B = in_sizes[0] / NW;  // 32768
    int threads = 128;
    int blocks = (B + threads - 1) / threads;
    qcnn_kernel<<<blocks, threads>>>(inputs, thetas, W, bias, out, B);
}